// round 4
// baseline (speedup 1.0000x reference)
#include <cuda_runtime.h>

// ---------------------------------------------------------------------------
// ARAP forward, split into:
//   pack   : xyz1/xyz2 -> interleaved float4 records (1 L2 sector per gather)
//   gather : per-vertex S = sum w d1 d2^T, P = sum w d1 d1^T, q = sum w d2^2
//            (register-capped, persistent grid-stride -> max occupancy on the
//             latency-bound random-gather phase)
//   solve  : Jacobi SVD -> R, algebraic energies (coalesced I/O, FMA-bound)
// ---------------------------------------------------------------------------

#define MAXV (4 * 65536)

__device__ float4 g_pack[2 * MAXV];   // [2t]: rest(x,y,z,0) [2t+1]: deformed
__device__ float4 g_acc[5 * MAXV];    // per-vertex {S(9),P(6),q(3)} padded to 20

__global__ void pack_kernel(const float* __restrict__ x1,
                            const float* __restrict__ x2,
                            int total) {
    int t = blockIdx.x * blockDim.x + threadIdx.x;
    if (t >= total) return;
    float a0 = x1[3 * t], a1 = x1[3 * t + 1], a2 = x1[3 * t + 2];
    float b0 = x2[3 * t], b1 = x2[3 * t + 1], b2 = x2[3 * t + 2];
    g_pack[2 * t]     = make_float4(a0, a1, a2, 0.f);
    g_pack[2 * t + 1] = make_float4(b0, b1, b2, 0.f);
}

// ---------------------------------------------------------------------------
// Phase A: gather + accumulate. Register-capped so 5 blocks/SM fit.
// ---------------------------------------------------------------------------
__global__ void __launch_bounds__(256, 5)
gather_kernel(const int*   __restrict__ nbrList,
              const int*   __restrict__ numN,
              const int*   __restrict__ accN,
              const float* __restrict__ wMat,
              int B, int N, int total)
{
    for (int t = blockIdx.x * blockDim.x + threadIdx.x; t < total;
         t += gridDim.x * blockDim.x) {
        int b = t / N;
        int i = t - b * N;
        int vbase2 = 2 * b * N;

        float4 c1 = g_pack[2 * t];
        float4 c2 = g_pack[2 * t + 1];
        int start = accN[i];
        int cnt   = numN[i];

        float S00=0.f,S01=0.f,S02=0.f,S10=0.f,S11=0.f,S12=0.f,S20=0.f,S21=0.f,S22=0.f;
        float p00=0.f,p01=0.f,p02=0.f,p11=0.f,p12=0.f,p22=0.f;
        float q0=0.f,q1=0.f,q2=0.f;

#define EDGE_ACC(j_, w_)                                                     \
    {                                                                        \
        const float4* pp = &g_pack[vbase2 + 2 * (j_)];                       \
        float4 p1v = pp[0], p2v = pp[1];                                     \
        float d1x = c1.x - p1v.x, d1y = c1.y - p1v.y, d1z = c1.z - p1v.z;    \
        float d2x = c2.x - p2v.x, d2y = c2.y - p2v.y, d2z = c2.z - p2v.z;    \
        float wx = (w_) * d1x, wy = (w_) * d1y, wz = (w_) * d1z;             \
        S00 += wx * d2x; S01 += wx * d2y; S02 += wx * d2z;                   \
        S10 += wy * d2x; S11 += wy * d2y; S12 += wy * d2z;                   \
        S20 += wz * d2x; S21 += wz * d2y; S22 += wz * d2z;                   \
        p00 += wx * d1x; p01 += wx * d1y; p02 += wx * d1z;                   \
        p11 += wy * d1y; p12 += wy * d1z; p22 += wz * d1z;                   \
        float vx = (w_) * d2x, vy = (w_) * d2y, vz = (w_) * d2z;             \
        q0 += vx * d2x; q1 += vy * d2y; q2 += vz * d2z;                      \
    }

        if (cnt == 16 && (start & 3) == 0) {
            const int4*   nb4 = (const int4*)(nbrList + start);
            const float4* wv4 = (const float4*)(wMat + start);
            #pragma unroll
            for (int g = 0; g < 4; g++) {
                int4   nb = nb4[g];
                float4 wv = wv4[g];
                EDGE_ACC(nb.x, wv.x)
                EDGE_ACC(nb.y, wv.y)
                EDGE_ACC(nb.z, wv.z)
                EDGE_ACC(nb.w, wv.w)
            }
        } else {
            for (int k = 0; k < cnt; k++) {
                int   j = nbrList[start + k];
                float w = wMat[start + k];
                EDGE_ACC(j, w)
            }
        }
#undef EDGE_ACC

        float4* acc = &g_acc[5 * t];
        acc[0] = make_float4(S00, S01, S02, S10);
        acc[1] = make_float4(S11, S12, S20, S21);
        acc[2] = make_float4(S22, p00, p01, p02);
        acc[3] = make_float4(p11, p12, p22, q0);
        acc[4] = make_float4(q1, q2, 0.f, 0.f);
    }
}

// ---------------------------------------------------------------------------
// Phase B: SVD + rotation + energies. Coalesced I/O, no gathers.
// ---------------------------------------------------------------------------
__device__ __forceinline__ void jrot(float A[3][3], float V[3][3], int p, int q) {
    float apq = A[p][q];
    if (fabsf(apq) > 1e-30f) {
        float app = A[p][p], aqq = A[q][q];
        float tau = (aqq - app) / (2.0f * apq);
        float tt  = copysignf(1.0f, tau) / (fabsf(tau) + sqrtf(1.0f + tau * tau));
        float c   = 1.0f / sqrtf(1.0f + tt * tt);
        float s   = tt * c;
        int r = 3 - p - q;
        float arp = A[r][p], arq = A[r][q];
        A[p][p] = app - tt * apq;
        A[q][q] = aqq + tt * apq;
        A[p][q] = 0.f; A[q][p] = 0.f;
        float nrp = c * arp - s * arq;
        float nrq = s * arp + c * arq;
        A[r][p] = nrp; A[p][r] = nrp;
        A[r][q] = nrq; A[q][r] = nrq;
        #pragma unroll
        for (int i = 0; i < 3; i++) {
            float vip = V[i][p], viq = V[i][q];
            V[i][p] = c * vip - s * viq;
            V[i][q] = s * vip + c * viq;
        }
    }
}

__device__ __forceinline__ void swap_col(float V[3][3], int a, int b) {
    #pragma unroll
    for (int i = 0; i < 3; i++) {
        float tmp = V[i][a]; V[i][a] = V[i][b]; V[i][b] = tmp;
    }
}

__global__ void __launch_bounds__(256)
solve_kernel(const float* __restrict__ arapW,
             float*       __restrict__ out,
             int total)
{
    int t = blockIdx.x * blockDim.x + threadIdx.x;
    if (t >= total) return;

    const float4* acc = &g_acc[5 * t];
    float4 a0 = acc[0], a1 = acc[1], a2 = acc[2], a3 = acc[3], a4 = acc[4];

    float S[3][3] = {{a0.x, a0.y, a0.z},
                     {a0.w, a1.x, a1.y},
                     {a1.z, a1.w, a2.x}};
    float p00 = a2.y, p01 = a2.z, p02 = a2.w;
    float p11 = a3.x, p12 = a3.y, p22 = a3.z;
    float q0  = a3.w, q1 = a4.x, q2 = a4.y;

    // Jacobi eigen of M = S^T S -> V
    float A[3][3];
    #pragma unroll
    for (int p = 0; p < 3; p++)
        #pragma unroll
        for (int q = 0; q < 3; q++)
            A[p][q] = S[0][p] * S[0][q] + S[1][p] * S[1][q] + S[2][p] * S[2][q];

    float V[3][3] = {{1.f,0.f,0.f},{0.f,1.f,0.f},{0.f,0.f,1.f}};
    #pragma unroll
    for (int sw = 0; sw < 6; sw++) {
        jrot(A, V, 0, 1);
        jrot(A, V, 0, 2);
        jrot(A, V, 1, 2);
    }

    if (A[0][0] < A[1][1]) { float tmp=A[0][0]; A[0][0]=A[1][1]; A[1][1]=tmp; swap_col(V,0,1); }
    if (A[0][0] < A[2][2]) { float tmp=A[0][0]; A[0][0]=A[2][2]; A[2][2]=tmp; swap_col(V,0,2); }
    if (A[1][1] < A[2][2]) { float tmp=A[1][1]; A[1][1]=A[2][2]; A[2][2]=tmp; swap_col(V,1,2); }

    float v0x=V[0][0], v0y=V[1][0], v0z=V[2][0];
    float v1x=V[0][1], v1y=V[1][1], v1z=V[2][1];
    float v2x=V[0][2], v2y=V[1][2], v2z=V[2][2];

    float u0x = S[0][0]*v0x + S[0][1]*v0y + S[0][2]*v0z;
    float u0y = S[1][0]*v0x + S[1][1]*v0y + S[1][2]*v0z;
    float u0z = S[2][0]*v0x + S[2][1]*v0y + S[2][2]*v0z;
    float u1x = S[0][0]*v1x + S[0][1]*v1y + S[0][2]*v1z;
    float u1y = S[1][0]*v1x + S[1][1]*v1y + S[1][2]*v1z;
    float u1z = S[2][0]*v1x + S[2][1]*v1y + S[2][2]*v1z;
    float u2x = S[0][0]*v2x + S[0][1]*v2y + S[0][2]*v2z;
    float u2y = S[1][0]*v2x + S[1][1]*v2y + S[1][2]*v2z;
    float u2z = S[2][0]*v2x + S[2][1]*v2y + S[2][2]*v2z;

    float n0 = rsqrtf(fmaxf(u0x*u0x + u0y*u0y + u0z*u0z, 1e-30f));
    float n1 = rsqrtf(fmaxf(u1x*u1x + u1y*u1y + u1z*u1z, 1e-30f));
    float n2 = rsqrtf(fmaxf(u2x*u2x + u2y*u2y + u2z*u2z, 1e-30f));
    u0x*=n0; u0y*=n0; u0z*=n0;
    u1x*=n1; u1y*=n1; u1z*=n1;
    u2x*=n2; u2y*=n2; u2z*=n2;

    float detS = S[0][0]*(S[1][1]*S[2][2] - S[1][2]*S[2][1])
               - S[0][1]*(S[1][0]*S[2][2] - S[1][2]*S[2][0])
               + S[0][2]*(S[1][0]*S[2][1] - S[1][1]*S[2][0]);
    float sgn = (detS < 0.f) ? -1.f : 1.f;
    u2x *= sgn; u2y *= sgn; u2z *= sgn;

    float R00 = v0x*u0x + v1x*u1x + v2x*u2x;
    float R01 = v0x*u0y + v1x*u1y + v2x*u2y;
    float R02 = v0x*u0z + v1x*u1z + v2x*u2z;
    float R10 = v0y*u0x + v1y*u1x + v2y*u2x;
    float R11 = v0y*u0y + v1y*u1y + v2y*u2y;
    float R12 = v0y*u0z + v1y*u1z + v2y*u2z;
    float R20 = v0z*u0x + v1z*u1x + v2z*u2x;
    float R21 = v0z*u0y + v1z*u1y + v2z*u2y;
    float R22 = v0z*u0z + v1z*u1z + v2z*u2z;

    // E_c = q_c - 2 sum_j R[c][j] S[j][c] + r_c^T P r_c
    float e0 = q0
        - 2.f * (R00*S[0][0] + R01*S[1][0] + R02*S[2][0])
        + R00*R00*p00 + R01*R01*p11 + R02*R02*p22
        + 2.f * (R00*R01*p01 + R00*R02*p02 + R01*R02*p12);
    float e1 = q1
        - 2.f * (R10*S[0][1] + R11*S[1][1] + R12*S[2][1])
        + R10*R10*p00 + R11*R11*p11 + R12*R12*p22
        + 2.f * (R10*R11*p01 + R10*R12*p02 + R11*R12*p12);
    float e2 = q2
        - 2.f * (R20*S[0][2] + R21*S[1][2] + R22*S[2][2])
        + R20*R20*p00 + R21*R21*p11 + R22*R22*p22
        + 2.f * (R20*R21*p01 + R20*R22*p02 + R21*R22*p12);
    e0 = fmaxf(e0, 0.f); e1 = fmaxf(e1, 0.f); e2 = fmaxf(e2, 0.f);

    float aw = arapW[0];
    size_t eo = (size_t)t * 3;
    out[eo + 0] = aw * e0;
    out[eo + 1] = aw * e1;
    out[eo + 2] = aw * e2;

    size_t ro = (size_t)total * 3 + (size_t)t * 9;
    out[ro + 0] = R00; out[ro + 1] = R01; out[ro + 2] = R02;
    out[ro + 3] = R10; out[ro + 4] = R11; out[ro + 5] = R12;
    out[ro + 6] = R20; out[ro + 7] = R21; out[ro + 8] = R22;
}

extern "C" void kernel_launch(void* const* d_in, const int* in_sizes, int n_in,
                              void* d_out, int out_size) {
    const float* xyz1 = (const float*)d_in[0];
    const float* xyz2 = (const float*)d_in[1];
    const int*   nbr  = (const int*)d_in[2];
    const int*   numN = (const int*)d_in[3];
    const int*   accN = (const int*)d_in[4];
    const float* wM   = (const float*)d_in[5];
    const float* aw   = (const float*)d_in[6];

    int N = in_sizes[3];                 // numNeighbors has N entries
    int B = in_sizes[0] / (3 * N);       // xyz1 is B*N*3
    int total = B * N;

    int threads = 256;
    int blocks = (total + threads - 1) / threads;
    pack_kernel<<<blocks, threads>>>(xyz1, xyz2, total);

    // persistent grid: 5 blocks/SM x 148 SMs (grid-stride covers any surplus)
    int gather_blocks = 148 * 5;
    gather_kernel<<<gather_blocks, threads>>>(nbr, numN, accN, wM, B, N, total);

    solve_kernel<<<blocks, threads>>>(aw, (float*)d_out, total);
}

// round 5
// speedup vs baseline: 1.4027x; 1.4027x over previous
#include <cuda_runtime.h>

// ---------------------------------------------------------------------------
// ARAP forward, monolithic single-pass (R2 structure) with:
//   - occupancy-capped main kernel: __launch_bounds__(256,5) -> 40 warps/SM
//   - smem-staged pack kernel (coalesced float4 in, packed float4 out)
// Per vertex: S = sum w d1 d2^T, P = sum w d1 d1^T, q = sum w d2^2 in ONE
// gather pass; Jacobi SVD of S^T S -> R; energies algebraically.
// ---------------------------------------------------------------------------

#define MAXV (4 * 65536)

// Packed per-(batch,vertex) record: [2t] rest (x,y,z,0), [2t+1] deformed.
// 32B-aligned pair => each neighbor gather touches one 32B sector.
__device__ float4 g_pack[2 * MAXV];

// Pack via shared staging: each block handles 256 vertices = 768 floats per
// array, loaded as 192 coalesced float4 per array.
__global__ void __launch_bounds__(256)
pack_kernel(const float* __restrict__ x1,
            const float* __restrict__ x2,
            int total) {
    __shared__ float s1[768];
    __shared__ float s2[768];
    int base = blockIdx.x * 256;            // first vertex of this block
    int tid  = threadIdx.x;

    int nvert = min(256, total - base);
    int nflt  = nvert * 3;

    if (((base * 3) & 3) == 0 && (nflt & 3) == 0) {
        const float4* p1 = (const float4*)(x1 + base * 3);
        const float4* p2 = (const float4*)(x2 + base * 3);
        int nv4 = nflt >> 2;               // <=192
        if (tid < nv4) {
            ((float4*)s1)[tid] = p1[tid];
            ((float4*)s2)[tid] = p2[tid];
        }
    } else {
        for (int k = tid; k < nflt; k += 256) {
            s1[k] = x1[base * 3 + k];
            s2[k] = x2[base * 3 + k];
        }
    }
    __syncthreads();

    if (tid < nvert) {
        int t = base + tid;
        g_pack[2 * t]     = make_float4(s1[3 * tid], s1[3 * tid + 1], s1[3 * tid + 2], 0.f);
        g_pack[2 * t + 1] = make_float4(s2[3 * tid], s2[3 * tid + 1], s2[3 * tid + 2], 0.f);
    }
}

__device__ __forceinline__ void jrot(float A[3][3], float V[3][3], int p, int q) {
    float apq = A[p][q];
    if (fabsf(apq) > 1e-30f) {
        float app = A[p][p], aqq = A[q][q];
        float tau = (aqq - app) / (2.0f * apq);
        float tt  = copysignf(1.0f, tau) / (fabsf(tau) + sqrtf(1.0f + tau * tau));
        float c   = 1.0f / sqrtf(1.0f + tt * tt);
        float s   = tt * c;
        int r = 3 - p - q;
        float arp = A[r][p], arq = A[r][q];
        A[p][p] = app - tt * apq;
        A[q][q] = aqq + tt * apq;
        A[p][q] = 0.f; A[q][p] = 0.f;
        float nrp = c * arp - s * arq;
        float nrq = s * arp + c * arq;
        A[r][p] = nrp; A[p][r] = nrp;
        A[r][q] = nrq; A[q][r] = nrq;
        #pragma unroll
        for (int i = 0; i < 3; i++) {
            float vip = V[i][p], viq = V[i][q];
            V[i][p] = c * vip - s * viq;
            V[i][q] = s * vip + c * viq;
        }
    }
}

__device__ __forceinline__ void swap_col(float V[3][3], int a, int b) {
    #pragma unroll
    for (int i = 0; i < 3; i++) {
        float tmp = V[i][a]; V[i][a] = V[i][b]; V[i][b] = tmp;
    }
}

__global__ void __launch_bounds__(256, 5)
arap_main(const int*   __restrict__ nbrList,
          const int*   __restrict__ numN,
          const int*   __restrict__ accN,
          const float* __restrict__ wMat,
          const float* __restrict__ arapW,
          float*       __restrict__ out,
          int B, int N)
{
    int t = blockIdx.x * blockDim.x + threadIdx.x;
    int total = B * N;
    if (t >= total) return;
    int b = t / N;
    int i = t - b * N;
    int vbase2 = 2 * (b * N);

    float4 c1 = g_pack[2 * t];
    float4 c2 = g_pack[2 * t + 1];
    int start = accN[i];
    int cnt   = numN[i];

    float S00=0.f,S01=0.f,S02=0.f,S10=0.f,S11=0.f,S12=0.f,S20=0.f,S21=0.f,S22=0.f;
    float p00=0.f,p01=0.f,p02=0.f,p11=0.f,p12=0.f,p22=0.f;
    float q0=0.f,q1=0.f,q2=0.f;

#define EDGE_ACC(j_, w_)                                                     \
    {                                                                        \
        const float4* pp = &g_pack[vbase2 + 2 * (j_)];                       \
        float4 p1v = pp[0], p2v = pp[1];                                     \
        float d1x = c1.x - p1v.x, d1y = c1.y - p1v.y, d1z = c1.z - p1v.z;    \
        float d2x = c2.x - p2v.x, d2y = c2.y - p2v.y, d2z = c2.z - p2v.z;    \
        float wx = (w_) * d1x, wy = (w_) * d1y, wz = (w_) * d1z;             \
        S00 += wx * d2x; S01 += wx * d2y; S02 += wx * d2z;                   \
        S10 += wy * d2x; S11 += wy * d2y; S12 += wy * d2z;                   \
        S20 += wz * d2x; S21 += wz * d2y; S22 += wz * d2z;                   \
        p00 += wx * d1x; p01 += wx * d1y; p02 += wx * d1z;                   \
        p11 += wy * d1y; p12 += wy * d1z; p22 += wz * d1z;                   \
        float vx = (w_) * d2x, vy = (w_) * d2y, vz = (w_) * d2z;             \
        q0 += vx * d2x; q1 += vy * d2y; q2 += vz * d2z;                      \
    }

    if (cnt == 16 && (start & 3) == 0) {
        const int4*   nb4 = (const int4*)(nbrList + start);
        const float4* wv4 = (const float4*)(wMat + start);
        #pragma unroll
        for (int g = 0; g < 4; g++) {
            int4   nb = nb4[g];
            float4 wv = wv4[g];
            EDGE_ACC(nb.x, wv.x)
            EDGE_ACC(nb.y, wv.y)
            EDGE_ACC(nb.z, wv.z)
            EDGE_ACC(nb.w, wv.w)
        }
    } else {
        for (int k = 0; k < cnt; k++) {
            int   j = nbrList[start + k];
            float w = wMat[start + k];
            EDGE_ACC(j, w)
        }
    }
#undef EDGE_ACC

    // ------------------- Jacobi eigen of M = S^T S -> V ----------------
    float S[3][3] = {{S00,S01,S02},{S10,S11,S12},{S20,S21,S22}};
    float A[3][3];
    #pragma unroll
    for (int p = 0; p < 3; p++)
        #pragma unroll
        for (int q = 0; q < 3; q++)
            A[p][q] = S[0][p] * S[0][q] + S[1][p] * S[1][q] + S[2][p] * S[2][q];

    float V[3][3] = {{1.f,0.f,0.f},{0.f,1.f,0.f},{0.f,0.f,1.f}};
    #pragma unroll
    for (int sw = 0; sw < 6; sw++) {
        jrot(A, V, 0, 1);
        jrot(A, V, 0, 2);
        jrot(A, V, 1, 2);
    }

    if (A[0][0] < A[1][1]) { float tmp=A[0][0]; A[0][0]=A[1][1]; A[1][1]=tmp; swap_col(V,0,1); }
    if (A[0][0] < A[2][2]) { float tmp=A[0][0]; A[0][0]=A[2][2]; A[2][2]=tmp; swap_col(V,0,2); }
    if (A[1][1] < A[2][2]) { float tmp=A[1][1]; A[1][1]=A[2][2]; A[2][2]=tmp; swap_col(V,1,2); }

    // u_j = normalize(S v_j)
    float v0x=V[0][0], v0y=V[1][0], v0z=V[2][0];
    float v1x=V[0][1], v1y=V[1][1], v1z=V[2][1];
    float v2x=V[0][2], v2y=V[1][2], v2z=V[2][2];

    float u0x = S[0][0]*v0x + S[0][1]*v0y + S[0][2]*v0z;
    float u0y = S[1][0]*v0x + S[1][1]*v0y + S[1][2]*v0z;
    float u0z = S[2][0]*v0x + S[2][1]*v0y + S[2][2]*v0z;
    float u1x = S[0][0]*v1x + S[0][1]*v1y + S[0][2]*v1z;
    float u1y = S[1][0]*v1x + S[1][1]*v1y + S[1][2]*v1z;
    float u1z = S[2][0]*v1x + S[2][1]*v1y + S[2][2]*v1z;
    float u2x = S[0][0]*v2x + S[0][1]*v2y + S[0][2]*v2z;
    float u2y = S[1][0]*v2x + S[1][1]*v2y + S[1][2]*v2z;
    float u2z = S[2][0]*v2x + S[2][1]*v2y + S[2][2]*v2z;

    float n0 = rsqrtf(fmaxf(u0x*u0x + u0y*u0y + u0z*u0z, 1e-30f));
    float n1 = rsqrtf(fmaxf(u1x*u1x + u1y*u1y + u1z*u1z, 1e-30f));
    float n2 = rsqrtf(fmaxf(u2x*u2x + u2y*u2y + u2z*u2z, 1e-30f));
    u0x*=n0; u0y*=n0; u0z*=n0;
    u1x*=n1; u1y*=n1; u1z*=n1;
    u2x*=n2; u2y*=n2; u2z*=n2;

    float detS = S[0][0]*(S[1][1]*S[2][2] - S[1][2]*S[2][1])
               - S[0][1]*(S[1][0]*S[2][2] - S[1][2]*S[2][0])
               + S[0][2]*(S[1][0]*S[2][1] - S[1][1]*S[2][0]);
    float sgn = (detS < 0.f) ? -1.f : 1.f;
    u2x *= sgn; u2y *= sgn; u2z *= sgn;

    // R = Vfix U^T
    float R00 = v0x*u0x + v1x*u1x + v2x*u2x;
    float R01 = v0x*u0y + v1x*u1y + v2x*u2y;
    float R02 = v0x*u0z + v1x*u1z + v2x*u2z;
    float R10 = v0y*u0x + v1y*u1x + v2y*u2x;
    float R11 = v0y*u0y + v1y*u1y + v2y*u2y;
    float R12 = v0y*u0z + v1y*u1z + v2y*u2z;
    float R20 = v0z*u0x + v1z*u1x + v2z*u2x;
    float R21 = v0z*u0y + v1z*u1y + v2z*u2y;
    float R22 = v0z*u0z + v1z*u1z + v2z*u2z;

    // E_c = q_c - 2 sum_j R[c][j] S[j][c] + r_c^T P r_c
    float e0 = q0
        - 2.f * (R00*S[0][0] + R01*S[1][0] + R02*S[2][0])
        + R00*R00*p00 + R01*R01*p11 + R02*R02*p22
        + 2.f * (R00*R01*p01 + R00*R02*p02 + R01*R02*p12);
    float e1 = q1
        - 2.f * (R10*S[0][1] + R11*S[1][1] + R12*S[2][1])
        + R10*R10*p00 + R11*R11*p11 + R12*R12*p22
        + 2.f * (R10*R11*p01 + R10*R12*p02 + R11*R12*p12);
    float e2 = q2
        - 2.f * (R20*S[0][2] + R21*S[1][2] + R22*S[2][2])
        + R20*R20*p00 + R21*R21*p11 + R22*R22*p22
        + 2.f * (R20*R21*p01 + R20*R22*p02 + R21*R22*p12);
    e0 = fmaxf(e0, 0.f); e1 = fmaxf(e1, 0.f); e2 = fmaxf(e2, 0.f);

    float aw = arapW[0];
    size_t eo = (size_t)t * 3;
    out[eo + 0] = aw * e0;
    out[eo + 1] = aw * e1;
    out[eo + 2] = aw * e2;

    size_t ro = (size_t)total * 3 + (size_t)t * 9;
    out[ro + 0] = R00; out[ro + 1] = R01; out[ro + 2] = R02;
    out[ro + 3] = R10; out[ro + 4] = R11; out[ro + 5] = R12;
    out[ro + 6] = R20; out[ro + 7] = R21; out[ro + 8] = R22;
}

extern "C" void kernel_launch(void* const* d_in, const int* in_sizes, int n_in,
                              void* d_out, int out_size) {
    const float* xyz1 = (const float*)d_in[0];
    const float* xyz2 = (const float*)d_in[1];
    const int*   nbr  = (const int*)d_in[2];
    const int*   numN = (const int*)d_in[3];
    const int*   accN = (const int*)d_in[4];
    const float* wM   = (const float*)d_in[5];
    const float* aw   = (const float*)d_in[6];

    int N = in_sizes[3];                 // numNeighbors has N entries
    int B = in_sizes[0] / (3 * N);       // xyz1 is B*N*3
    int total = B * N;

    int threads = 256;
    int blocks = (total + threads - 1) / threads;
    pack_kernel<<<blocks, threads>>>(xyz1, xyz2, total);
    arap_main<<<blocks, threads>>>(nbr, numN, accN, wM, aw, (float*)d_out, B, N);
}

// round 6
// speedup vs baseline: 1.9560x; 1.3944x over previous
#include <cuda_runtime.h>

// ---------------------------------------------------------------------------
// ARAP forward — batch-interleaved gather layout.
// g_pack2: per-vertex 128B line = [b0.rest, b0.def, b1.rest, b1.def, ...]
// Thread t -> vertex i = t/B, batch b = t%B. For B=4, lanes 4g..4g+3 of a
// warp share vertex i, so each gather LDG.128 touches 8 distinct lines per
// warp instead of 32 (4x fewer L1 wavefronts).
// Single gather pass accumulates S, P, q; Jacobi SVD -> R; algebraic energies.
// ---------------------------------------------------------------------------

#define MAXV (4 * 65536)

// 2 float4 per (vertex,batch) record, batch-innermost: index = 2*(j*B + b).
__device__ float4 g_pack2[2 * MAXV];

// Specialized B==4 pack: 64 vertices x 4 batches per block, smem-staged.
__global__ void __launch_bounds__(256)
pack4_smem(const float* __restrict__ x1, const float* __restrict__ x2, int N) {
    __shared__ float s1[4 * 193];   // stride 193 to avoid bank conflicts
    __shared__ float s2[4 * 193];
    int j0  = blockIdx.x * 64;
    int tid = threadIdx.x;

    for (int idx = tid; idx < 768; idx += 256) {
        int b = idx / 192, k = idx - b * 192;
        s1[b * 193 + k] = x1[((size_t)b * N + j0) * 3 + k];
        s2[b * 193 + k] = x2[((size_t)b * N + j0) * 3 + k];
    }
    __syncthreads();

    int v = tid >> 2, b = tid & 3;
    int j = j0 + v;
    int si = b * 193 + v * 3;
    int t = j * 4 + b;
    g_pack2[2 * t]     = make_float4(s1[si], s1[si + 1], s1[si + 2], 0.f);
    g_pack2[2 * t + 1] = make_float4(s2[si], s2[si + 1], s2[si + 2], 0.f);
}

// Generic fallback pack (any B).
__global__ void pack_naive(const float* __restrict__ x1,
                           const float* __restrict__ x2,
                           int B, int N) {
    int t = blockIdx.x * blockDim.x + threadIdx.x;
    if (t >= B * N) return;
    int i = t / B, b = t - i * B;
    const float* p1 = x1 + ((size_t)b * N + i) * 3;
    const float* p2 = x2 + ((size_t)b * N + i) * 3;
    g_pack2[2 * t]     = make_float4(p1[0], p1[1], p1[2], 0.f);
    g_pack2[2 * t + 1] = make_float4(p2[0], p2[1], p2[2], 0.f);
}

__device__ __forceinline__ void jrot(float A[3][3], float V[3][3], int p, int q) {
    float apq = A[p][q];
    if (fabsf(apq) > 1e-30f) {
        float app = A[p][p], aqq = A[q][q];
        float tau = (aqq - app) / (2.0f * apq);
        float tt  = copysignf(1.0f, tau) / (fabsf(tau) + sqrtf(1.0f + tau * tau));
        float c   = 1.0f / sqrtf(1.0f + tt * tt);
        float s   = tt * c;
        int r = 3 - p - q;
        float arp = A[r][p], arq = A[r][q];
        A[p][p] = app - tt * apq;
        A[q][q] = aqq + tt * apq;
        A[p][q] = 0.f; A[q][p] = 0.f;
        float nrp = c * arp - s * arq;
        float nrq = s * arp + c * arq;
        A[r][p] = nrp; A[p][r] = nrp;
        A[r][q] = nrq; A[q][r] = nrq;
        #pragma unroll
        for (int i = 0; i < 3; i++) {
            float vip = V[i][p], viq = V[i][q];
            V[i][p] = c * vip - s * viq;
            V[i][q] = s * vip + c * viq;
        }
    }
}

__device__ __forceinline__ void swap_col(float V[3][3], int a, int b) {
    #pragma unroll
    for (int i = 0; i < 3; i++) {
        float tmp = V[i][a]; V[i][a] = V[i][b]; V[i][b] = tmp;
    }
}

__global__ void __launch_bounds__(256)
arap_main(const int*   __restrict__ nbrList,
          const int*   __restrict__ numN,
          const int*   __restrict__ accN,
          const float* __restrict__ wMat,
          const float* __restrict__ arapW,
          float*       __restrict__ out,
          int B, int N)
{
    int t = blockIdx.x * blockDim.x + threadIdx.x;
    int total = B * N;
    if (t >= total) return;
    int i = t / B;              // vertex (B=4: lanes 4g..4g+3 share i)
    int b = t - i * B;          // batch

    float4 c1 = g_pack2[2 * t];
    float4 c2 = g_pack2[2 * t + 1];
    int start = accN[i];
    int cnt   = numN[i];

    float S00=0.f,S01=0.f,S02=0.f,S10=0.f,S11=0.f,S12=0.f,S20=0.f,S21=0.f,S22=0.f;
    float p00=0.f,p01=0.f,p02=0.f,p11=0.f,p12=0.f,p22=0.f;
    float q0=0.f,q1=0.f,q2=0.f;

#define EDGE_ACC(j_, w_)                                                     \
    {                                                                        \
        const float4* pp = &g_pack2[2 * ((j_) * B + b)];                     \
        float4 p1v = pp[0], p2v = pp[1];                                     \
        float d1x = c1.x - p1v.x, d1y = c1.y - p1v.y, d1z = c1.z - p1v.z;    \
        float d2x = c2.x - p2v.x, d2y = c2.y - p2v.y, d2z = c2.z - p2v.z;    \
        float wx = (w_) * d1x, wy = (w_) * d1y, wz = (w_) * d1z;             \
        S00 += wx * d2x; S01 += wx * d2y; S02 += wx * d2z;                   \
        S10 += wy * d2x; S11 += wy * d2y; S12 += wy * d2z;                   \
        S20 += wz * d2x; S21 += wz * d2y; S22 += wz * d2z;                   \
        p00 += wx * d1x; p01 += wx * d1y; p02 += wx * d1z;                   \
        p11 += wy * d1y; p12 += wy * d1z; p22 += wz * d1z;                   \
        float vx = (w_) * d2x, vy = (w_) * d2y, vz = (w_) * d2z;             \
        q0 += vx * d2x; q1 += vy * d2y; q2 += vz * d2z;                      \
    }

    if (cnt == 16 && (start & 3) == 0) {
        const int4*   nb4 = (const int4*)(nbrList + start);
        const float4* wv4 = (const float4*)(wMat + start);
        #pragma unroll
        for (int g = 0; g < 4; g++) {
            int4   nb = nb4[g];
            float4 wv = wv4[g];
            EDGE_ACC(nb.x, wv.x)
            EDGE_ACC(nb.y, wv.y)
            EDGE_ACC(nb.z, wv.z)
            EDGE_ACC(nb.w, wv.w)
        }
    } else {
        for (int k = 0; k < cnt; k++) {
            int   j = nbrList[start + k];
            float w = wMat[start + k];
            EDGE_ACC(j, w)
        }
    }
#undef EDGE_ACC

    // ------------------- Jacobi eigen of M = S^T S -> V ----------------
    float S[3][3] = {{S00,S01,S02},{S10,S11,S12},{S20,S21,S22}};
    float A[3][3];
    #pragma unroll
    for (int p = 0; p < 3; p++)
        #pragma unroll
        for (int q = 0; q < 3; q++)
            A[p][q] = S[0][p] * S[0][q] + S[1][p] * S[1][q] + S[2][p] * S[2][q];

    float V[3][3] = {{1.f,0.f,0.f},{0.f,1.f,0.f},{0.f,0.f,1.f}};
    #pragma unroll
    for (int sw = 0; sw < 6; sw++) {
        jrot(A, V, 0, 1);
        jrot(A, V, 0, 2);
        jrot(A, V, 1, 2);
    }

    if (A[0][0] < A[1][1]) { float tmp=A[0][0]; A[0][0]=A[1][1]; A[1][1]=tmp; swap_col(V,0,1); }
    if (A[0][0] < A[2][2]) { float tmp=A[0][0]; A[0][0]=A[2][2]; A[2][2]=tmp; swap_col(V,0,2); }
    if (A[1][1] < A[2][2]) { float tmp=A[1][1]; A[1][1]=A[2][2]; A[2][2]=tmp; swap_col(V,1,2); }

    // u_j = normalize(S v_j)
    float v0x=V[0][0], v0y=V[1][0], v0z=V[2][0];
    float v1x=V[0][1], v1y=V[1][1], v1z=V[2][1];
    float v2x=V[0][2], v2y=V[1][2], v2z=V[2][2];

    float u0x = S[0][0]*v0x + S[0][1]*v0y + S[0][2]*v0z;
    float u0y = S[1][0]*v0x + S[1][1]*v0y + S[1][2]*v0z;
    float u0z = S[2][0]*v0x + S[2][1]*v0y + S[2][2]*v0z;
    float u1x = S[0][0]*v1x + S[0][1]*v1y + S[0][2]*v1z;
    float u1y = S[1][0]*v1x + S[1][1]*v1y + S[1][2]*v1z;
    float u1z = S[2][0]*v1x + S[2][1]*v1y + S[2][2]*v1z;
    float u2x = S[0][0]*v2x + S[0][1]*v2y + S[0][2]*v2z;
    float u2y = S[1][0]*v2x + S[1][1]*v2y + S[1][2]*v2z;
    float u2z = S[2][0]*v2x + S[2][1]*v2y + S[2][2]*v2z;

    float n0 = rsqrtf(fmaxf(u0x*u0x + u0y*u0y + u0z*u0z, 1e-30f));
    float n1 = rsqrtf(fmaxf(u1x*u1x + u1y*u1y + u1z*u1z, 1e-30f));
    float n2 = rsqrtf(fmaxf(u2x*u2x + u2y*u2y + u2z*u2z, 1e-30f));
    u0x*=n0; u0y*=n0; u0z*=n0;
    u1x*=n1; u1y*=n1; u1z*=n1;
    u2x*=n2; u2y*=n2; u2z*=n2;

    float detS = S[0][0]*(S[1][1]*S[2][2] - S[1][2]*S[2][1])
               - S[0][1]*(S[1][0]*S[2][2] - S[1][2]*S[2][0])
               + S[0][2]*(S[1][0]*S[2][1] - S[1][1]*S[2][0]);
    float sgn = (detS < 0.f) ? -1.f : 1.f;
    u2x *= sgn; u2y *= sgn; u2z *= sgn;

    // R = Vfix U^T
    float R00 = v0x*u0x + v1x*u1x + v2x*u2x;
    float R01 = v0x*u0y + v1x*u1y + v2x*u2y;
    float R02 = v0x*u0z + v1x*u1z + v2x*u2z;
    float R10 = v0y*u0x + v1y*u1x + v2y*u2x;
    float R11 = v0y*u0y + v1y*u1y + v2y*u2y;
    float R12 = v0y*u0z + v1y*u1z + v2y*u2z;
    float R20 = v0z*u0x + v1z*u1x + v2z*u2x;
    float R21 = v0z*u0y + v1z*u1y + v2z*u2y;
    float R22 = v0z*u0z + v1z*u1z + v2z*u2z;

    // E_c = q_c - 2 sum_j R[c][j] S[j][c] + r_c^T P r_c
    float e0 = q0
        - 2.f * (R00*S[0][0] + R01*S[1][0] + R02*S[2][0])
        + R00*R00*p00 + R01*R01*p11 + R02*R02*p22
        + 2.f * (R00*R01*p01 + R00*R02*p02 + R01*R02*p12);
    float e1 = q1
        - 2.f * (R10*S[0][1] + R11*S[1][1] + R12*S[2][1])
        + R10*R10*p00 + R11*R11*p11 + R12*R12*p22
        + 2.f * (R10*R11*p01 + R10*R12*p02 + R11*R12*p12);
    float e2 = q2
        - 2.f * (R20*S[0][2] + R21*S[1][2] + R22*S[2][2])
        + R20*R20*p00 + R21*R21*p11 + R22*R22*p22
        + 2.f * (R20*R21*p01 + R20*R22*p02 + R21*R22*p12);
    e0 = fmaxf(e0, 0.f); e1 = fmaxf(e1, 0.f); e2 = fmaxf(e2, 0.f);

    // -------- outputs: original ordering t_old = b*N + i -----------------
    float aw = arapW[0];
    int told = b * N + i;
    size_t eo = (size_t)told * 3;
    out[eo + 0] = aw * e0;
    out[eo + 1] = aw * e1;
    out[eo + 2] = aw * e2;

    size_t ro = (size_t)total * 3 + (size_t)told * 9;
    out[ro + 0] = R00; out[ro + 1] = R01; out[ro + 2] = R02;
    out[ro + 3] = R10; out[ro + 4] = R11; out[ro + 5] = R12;
    out[ro + 6] = R20; out[ro + 7] = R21; out[ro + 8] = R22;
}

extern "C" void kernel_launch(void* const* d_in, const int* in_sizes, int n_in,
                              void* d_out, int out_size) {
    const float* xyz1 = (const float*)d_in[0];
    const float* xyz2 = (const float*)d_in[1];
    const int*   nbr  = (const int*)d_in[2];
    const int*   numN = (const int*)d_in[3];
    const int*   accN = (const int*)d_in[4];
    const float* wM   = (const float*)d_in[5];
    const float* aw   = (const float*)d_in[6];

    int N = in_sizes[3];                 // numNeighbors has N entries
    int B = in_sizes[0] / (3 * N);       // xyz1 is B*N*3
    int total = B * N;

    int threads = 256;
    int blocks = (total + threads - 1) / threads;

    if (B == 4 && (N & 63) == 0) {
        pack4_smem<<<N / 64, threads>>>(xyz1, xyz2, N);
    } else {
        pack_naive<<<blocks, threads>>>(xyz1, xyz2, B, N);
    }
    arap_main<<<blocks, threads>>>(nbr, numN, accN, wM, aw, (float*)d_out, B, N);
}